// round 16
// baseline (speedup 1.0000x reference)
#include <cuda_runtime.h>
#include <cuda_bf16.h>
#include <float.h>
#include <math.h>
#include <stdint.h>

#define HW 16384
#define Dm 256
#define Bm 4
#define NBLK 128

// ---------------- scratch ----------------------------------------------------
__device__ float g_x[Bm * HW * Dm];
__device__ float g_proj[Bm * HW * Dm];
__device__ __nv_bfloat16 g_fh[Bm * HW * Dm];
__device__ __nv_bfloat16 g_fl[Bm * HW * Dm];
__device__ __nv_bfloat16 g_xh[Bm * HW * Dm];
__device__ __nv_bfloat16 g_xl[Bm * HW * Dm];
__device__ __nv_bfloat16 g_w1h[Dm * Dm], g_w1l[Dm * Dm];
__device__ __nv_bfloat16 g_w2h[Dm * Dm], g_w2l[Dm * Dm];
__device__ float g_s[Dm];
__device__ float g_c[Dm];
__device__ unsigned char g_m1[Bm * HW];
__device__ unsigned char g_m0[Bm * HW];
__device__ unsigned char g_sel[Bm * HW];
__device__ float g_ps[Dm * 512];
__device__ float g_pq[Dm * 512];
__device__ float g_pfg[Bm * Dm * NBLK];
__device__ float g_pbg[Bm * Dm * NBLK];
__device__ float g_mfg[Bm * Dm];
__device__ float g_mbg[Bm * Dm];
// selection outputs
__device__ int g_aidx[8 * 32];
__device__ float g_aflag[8 * 32];
__device__ int g_pidx[8 * 64];
__device__ float g_pflag[8 * 64];
__device__ int g_nidx[8 * 64];
__device__ float g_nflag[8 * 64];
__device__ int g_cA[8], g_cB[8];
__device__ float g_dacc[8 * 4 * 32];

// ---------------- block reduction --------------------------------------------
__device__ __forceinline__ float blk_sum(volatile float* scratch, float v, int tid) {
    int lane = tid & 31, w = tid >> 5;
#pragma unroll
    for (int off = 16; off; off >>= 1) v += __shfl_down_sync(0xffffffffu, v, off);
    if (lane == 0) scratch[w] = v;
    __syncthreads();
    if (w == 0) {
        v = (lane < 8) ? scratch[lane] : 0.f;
#pragma unroll
        for (int off = 4; off; off >>= 1) v += __shfl_down_sync(0xffffffffu, v, off);
        if (lane == 0) scratch[32] = v;
    }
    __syncthreads();
    return scratch[32];
}

// ---------------- bf16 hi/lo split -------------------------------------------
__device__ __forceinline__ void split2(float a, float b, uint32_t& h, uint32_t& l) {
    __nv_bfloat16 ah = __float2bfloat16_rn(a), bh = __float2bfloat16_rn(b);
    float ar = a - __bfloat162float(ah), br = b - __bfloat162float(bh);
    __nv_bfloat16 al = __float2bfloat16_rn(ar), bl = __float2bfloat16_rn(br);
    h = (uint32_t)*(unsigned short*)&ah | ((uint32_t)*(unsigned short*)&bh << 16);
    l = (uint32_t)*(unsigned short*)&al | ((uint32_t)*(unsigned short*)&bl << 16);
}

__device__ __forceinline__ void mma16816(float* c, const uint32_t* a, uint32_t b0, uint32_t b1) {
    asm volatile(
        "mma.sync.aligned.m16n8k16.row.col.f32.bf16.bf16.f32 "
        "{%0,%1,%2,%3}, {%4,%5,%6,%7}, {%8,%9}, {%0,%1,%2,%3};"
        : "+f"(c[0]), "+f"(c[1]), "+f"(c[2]), "+f"(c[3])
        : "r"(a[0]), "r"(a[1]), "r"(a[2]), "r"(a[3]), "r"(b0), "r"(b1));
}

__device__ __forceinline__ void ldsm_x4(uint32_t* r, uint32_t addr) {
    asm volatile("ldmatrix.sync.aligned.m8n8.x4.shared.b16 {%0,%1,%2,%3}, [%4];"
                 : "=r"(r[0]), "=r"(r[1]), "=r"(r[2]), "=r"(r[3])
                 : "r"(addr));
}
__device__ __forceinline__ void ldsm_x2(uint32_t& r0, uint32_t& r1, uint32_t addr) {
    asm volatile("ldmatrix.sync.aligned.m8n8.x2.shared.b16 {%0,%1}, [%2];"
                 : "=r"(r0), "=r"(r1)
                 : "r"(addr));
}

#define CP16(dst_u32, src_ptr) \
    asm volatile("cp.async.cg.shared.global [%0], [%1], 16;" ::"r"(dst_u32), "l"(src_ptr))
#define CP_COMMIT() asm volatile("cp.async.commit_group;" ::: "memory")
#define CP_WAIT1() asm volatile("cp.async.wait_group 1;" ::: "memory")
#define CP_WAIT0() asm volatile("cp.async.wait_group 0;" ::: "memory")

// ---------------- fused prologue: masks(+sel clear) + splitw + split_feat -----
__global__ __launch_bounds__(256) void k_pre(const float* __restrict__ prob_ori,
                                             const float* __restrict__ prob_aug,
                                             const float* __restrict__ unc,
                                             const int* __restrict__ labels,
                                             const float* __restrict__ w1,
                                             const float* __restrict__ w2,
                                             const float* __restrict__ feat) {
    __shared__ float tile[64 * 65];
    int blk = blockIdx.x;
    int tid = threadIdx.x;
    if (blk < 256) {  // masks + sel clear
        int idx = blk * 256 + tid;
        int b = idx >> 14;
        int hw = idx & (HW - 1);
        const float* po = prob_ori + (size_t)b * 2 * HW;
        const float* pa = prob_aug + (size_t)b * 2 * HW;
        int io = po[HW + hw] > po[hw];
        int ia = pa[HW + hw] > pa[hw];
        bool rel = (io == ia);
        bool diff = unc[idx] > 0.5f;
        int lab = labels[idx];
        bool valid = rel && diff;
        g_m1[idx] = (unsigned char)(valid && lab == 1);
        g_m0[idx] = (unsigned char)(valid && lab == 0);
        g_sel[idx] = 0;
        return;
    }
    if (blk < 384) {  // splitw
        int lin = (blk - 256) * 256 + tid;
#pragma unroll
        for (int s = 0; s < 2; s++) {
            const float* w = s ? w2 : w1;
            uint32_t* oh = (uint32_t*)(s ? g_w2h : g_w1h);
            uint32_t* ol = (uint32_t*)(s ? g_w2l : g_w1l);
            float a = w[2 * lin], b = w[2 * lin + 1];
            uint32_t h, l;
            split2(a, b, h, l);
            oh[lin] = h;
            ol[lin] = l;
        }
        return;
    }
    // split_feat
    int fb = blk - 384;
    int bxi = fb & 255, bzi = fb >> 8;
    int n0 = bxi * 64;
    int d0 = (bzi & 3) * 64;
    int b = bzi >> 2;
    const float* src = feat + ((size_t)b * Dm + d0) * HW + n0;
#pragma unroll
    for (int it = 0; it < 4; it++) {
        int lin = it * 256 + tid;
        int r = lin >> 4, c4 = lin & 15;
        float4 v = *(const float4*)(src + (size_t)r * HW + c4 * 4);
        tile[r * 65 + c4 * 4 + 0] = v.x;
        tile[r * 65 + c4 * 4 + 1] = v.y;
        tile[r * 65 + c4 * 4 + 2] = v.z;
        tile[r * 65 + c4 * 4 + 3] = v.w;
    }
    __syncthreads();
    uint32_t* oh = (uint32_t*)g_fh;
    uint32_t* ol = (uint32_t*)g_fl;
#pragma unroll
    for (int it = 0; it < 8; it++) {
        int lin = it * 256 + tid;
        int n = lin >> 5, c = lin & 31;
        float v0 = tile[(2 * c) * 65 + n];
        float v1 = tile[(2 * c + 1) * 65 + n];
        uint32_t h, l;
        split2(v0, v1, h, l);
        size_t o = (((size_t)b * HW + n0 + n) * 256 + d0) / 2 + c;
        oh[o] = h;
        ol[o] = l;
    }
}

// ---------------- bn+relu+split (16 floats/thread, MLP=4) ---------------------
__global__ __launch_bounds__(256) void k_bnsplit() {
    __shared__ float scs[256], scc[256];
    int tid = threadIdx.x;
    scs[tid] = g_s[tid];
    scc[tid] = g_c[tid];
    __syncthreads();
    size_t row = (size_t)blockIdx.x * 16 + (tid >> 4);
    int d0 = (tid & 15) * 16;
    const float* src = g_x + row * 256 + d0;
    float4 q0 = *(const float4*)src;
    float4 q1 = *(const float4*)(src + 4);
    float4 q2 = *(const float4*)(src + 8);
    float4 q3 = *(const float4*)(src + 12);
    float v[16] = {q0.x, q0.y, q0.z, q0.w, q1.x, q1.y, q1.z, q1.w,
                   q2.x, q2.y, q2.z, q2.w, q3.x, q3.y, q3.z, q3.w};
#pragma unroll
    for (int j = 0; j < 16; j++) v[j] = fmaxf(fmaf(scs[d0 + j], v[j], scc[d0 + j]), 0.f);
    uint32_t H[8], L[8];
#pragma unroll
    for (int j = 0; j < 8; j++) split2(v[2 * j], v[2 * j + 1], H[j], L[j]);
    size_t o = row * 128 + d0 / 2;
    *(uint4*)&((uint32_t*)g_xh)[o] = make_uint4(H[0], H[1], H[2], H[3]);
    *(uint4*)&((uint32_t*)g_xh)[o + 4] = make_uint4(H[4], H[5], H[6], H[7]);
    *(uint4*)&((uint32_t*)g_xl)[o] = make_uint4(L[0], L[1], L[2], L[3]);
    *(uint4*)&((uint32_t*)g_xl)[o + 4] = make_uint4(L[4], L[5], L[6], L[7]);
}

// ---------------- selection (smem struct + helpers) ---------------------------
struct PairS {
    unsigned short listA[HW];
    unsigned short listN[HW];
    unsigned long long sbuf[512];
    int hist[256];
    float red[34];
    int redi[34];
    int cidx[128];
    float cflag[128];
    int cntA, cntN, coll, bstar;
    float bestv;
    int besti;
};

__device__ __forceinline__ void pair_argmax(PairS* S, float v, int i, int tid) {
    int lane = tid & 31, w = tid >> 5;
#pragma unroll
    for (int off = 16; off; off >>= 1) {
        float ov = __shfl_down_sync(0xffffffffu, v, off);
        int oi = __shfl_down_sync(0xffffffffu, i, off);
        if (ov > v || (ov == v && oi < i)) { v = ov; i = oi; }
    }
    if (lane == 0) { S->red[w] = v; S->redi[w] = i; }
    __syncthreads();
    if (w == 0) {
        v = (lane < 8) ? S->red[lane] : -FLT_MAX;
        i = (lane < 8) ? S->redi[lane] : 0x7FFFFFFF;
#pragma unroll
        for (int off = 4; off; off >>= 1) {
            float ov = __shfl_down_sync(0xffffffffu, v, off);
            int oi = __shfl_down_sync(0xffffffffu, i, off);
            if (ov > v || (ov == v && oi < i)) { v = ov; i = oi; }
        }
        if (lane == 0) { S->bestv = v; S->besti = i; }
    }
    __syncthreads();
}

__device__ void select_topk(PairS* S, const unsigned short* list, int cnt,
                            const float* __restrict__ key, int K, int* oidx, float* oflag,
                            int tid) {
    float lastv = FLT_MAX;
    int lasti = -1;
    for (int kk = 0; kk < K; kk++) {
        float bv = -FLT_MAX;
        int bi = 0x7FFFFFFF;
        for (int ii = tid; ii < cnt; ii += 256) {
            int idx = list[ii];
            float v = key[idx];
            if (v < lastv || (v == lastv && idx > lasti)) {
                if (v > bv || (v == bv && idx < bi)) { bv = v; bi = idx; }
            }
        }
        pair_argmax(S, bv, bi, tid);
        float gbv = S->bestv;
        int gbi = S->besti;
        if (gbv > -FLT_MAX) {
            lastv = gbv;
            lasti = gbi;
            if (tid == 0) { oidx[kk] = gbi; oflag[kk] = 1.f; }
        } else {
            lastv = -FLT_MAX;
            lasti = 0x7FFFFFFF;
            if (tid == 0) { oidx[kk] = 0; oflag[kk] = 0.f; }
        }
        __syncthreads();
    }
}

__device__ void bitonic_desc(PairS* S, int n, int tid) {
    for (int k = 2; k <= n; k <<= 1)
        for (int j = k >> 1; j > 0; j >>= 1) {
            for (int t = tid; t < n; t += 256) {
                int ixj = t ^ j;
                if (ixj > t) {
                    unsigned long long x = S->sbuf[t], y = S->sbuf[ixj];
                    bool desc = ((t & k) == 0);
                    if (desc ? (x < y) : (x > y)) {
                        S->sbuf[t] = y;
                        S->sbuf[ixj] = x;
                    }
                }
            }
            __syncthreads();
        }
}

__device__ void radix_select(PairS* S, const unsigned short* list, int cnt,
                             const float* __restrict__ key, int K, int* oidx, float* oflag,
                             int tid) {
    int target = min(K, cnt);
    if (target == 0) {
        for (int kk = tid; kk < K; kk += 256) { oidx[kk] = 0; oflag[kk] = 0.f; }
        __syncthreads();
        return;
    }
    S->hist[tid] = 0;
    __syncthreads();
    for (int ii = tid; ii < cnt; ii += 256) {
        float r = key[list[ii]];
        int b = (int)(r * 256.f);
        b = b < 0 ? 0 : (b > 255 ? 255 : b);
        atomicAdd(&S->hist[b], 1);
    }
    __syncthreads();
    if (tid == 0) {
        int acc = 0, bs = 0;
        for (int b = 255; b >= 0; b--) {
            acc += S->hist[b];
            if (acc >= target) { bs = b; break; }
        }
        S->bstar = bs;
        S->coll = 0;
    }
    __syncthreads();
    int bstar = S->bstar;
    for (int ii = tid; ii < cnt; ii += 256) {
        int idx = list[ii];
        float r = key[idx];
        int b = (int)(r * 256.f);
        b = b < 0 ? 0 : (b > 255 ? 255 : b);
        if (b >= bstar) {
            int p = atomicAdd(&S->coll, 1);
            if (p < 512)
                S->sbuf[p] = ((unsigned long long)__float_as_uint(r) << 32) |
                             (unsigned long long)(unsigned int)(~(unsigned int)idx);
        }
    }
    __syncthreads();
    int coll = S->coll;
    if (coll > 512) {
        select_topk(S, list, cnt, key, K, oidx, oflag, tid);
        return;
    }
    int n = 1;
    while (n < coll) n <<= 1;
    for (int i = coll + tid; i < n; i += 256) S->sbuf[i] = 0ull;
    __syncthreads();
    bitonic_desc(S, n, tid);
    for (int kk = tid; kk < K; kk += 256) {
        if (kk < target) {
            oidx[kk] = (int)(~(unsigned int)(S->sbuf[kk] & 0xFFFFFFFFull));
            oflag[kk] = 1.f;
        } else {
            oidx[kk] = 0;
            oflag[kk] = 0.f;
        }
    }
    __syncthreads();
}

__device__ void hard_select(PairS* S, const float* __restrict__ ub, int* oidx, float* oflag,
                            int tid) {
    if (tid < 128) {
        unsigned long long kv;
        if (S->cflag[tid] != 0.f) {
            unsigned int u = __float_as_uint(ub[S->cidx[tid]]) + 1u;
            kv = ((unsigned long long)u << 32) |
                 (unsigned long long)(unsigned int)(~(unsigned int)tid);
        } else {
            kv = (unsigned long long)(unsigned int)(~(unsigned int)tid);
        }
        S->sbuf[tid] = kv;
    }
    __syncthreads();
    bitonic_desc(S, 128, tid);
    if (tid < 64) {
        int t = (int)((~(unsigned int)(S->sbuf[tid] & 0xFFFFFFFFull)) & 127u);
        oidx[tid] = S->cidx[t];
        oflag[tid] = S->cflag[t];
    }
    __syncthreads();
}

__device__ void do_select(char* smraw, int task, const float* unc, const float* r_anc,
                          const float* r_pos, const float* r_neg) {
    PairS* S = (PairS*)smraw;
    int b = task >> 1, c = task & 1;
    int tid = threadIdx.x;
    const unsigned char* am = (c == 0 ? g_m1 : g_m0) + b * HW;
    const unsigned char* nm = (c == 0 ? g_m0 : g_m1) + b * HW;

    if (tid == 0) { S->cntA = 0; S->cntN = 0; }
    __syncthreads();
    for (int i = tid; i < HW; i += 256) {
        if (am[i]) { int p = atomicAdd(&S->cntA, 1); S->listA[p] = (unsigned short)i; }
        if (nm[i]) { int p = atomicAdd(&S->cntN, 1); S->listN[p] = (unsigned short)i; }
    }
    __syncthreads();
    int cntA = S->cntA, cntN = S->cntN;

    const float* ra = r_anc + ((size_t)b * 2 + c) * HW;
    const float* rp = r_pos + ((size_t)b * 2 + c) * HW;
    const float* rn = r_neg + ((size_t)b * 2 + c) * HW;
    const float* ub = unc + (size_t)b * HW;

    radix_select(S, S->listA, cntA, ra, 32, g_aidx + task * 32, g_aflag + task * 32, tid);
    radix_select(S, S->listA, cntA, rp, 128, S->cidx, S->cflag, tid);
    hard_select(S, ub, g_pidx + task * 64, g_pflag + task * 64, tid);
    radix_select(S, S->listN, cntN, rn, 128, S->cidx, S->cflag, tid);
    hard_select(S, ub, g_nidx + task * 64, g_nflag + task * 64, tid);

    // mark selected rows for GEMM2's predicated g_proj writes (benign races: all write 1)
    if (tid < 32) g_sel[b * HW + g_aidx[task * 32 + tid]] = 1;
    if (tid < 64) g_sel[b * HW + g_pidx[task * 64 + tid]] = 1;
    if (tid < 64) g_sel[b * HW + g_nidx[task * 64 + tid]] = 1;

    if (tid == 0) {
        g_cA[task] = cntA;
        g_cB[task] = cntN;
    }
}

// ---------------- pure-bf16 HMMA GEMM ----------------------------------------
#define ROWW 20
#define MATW (128 * ROWW)
#define STAGEW (4 * MATW)
#define OFF_EXT (2 * STAGEW)
#define GEMM_SMEM ((OFF_EXT + 1536) * 4)  // 88064 bytes (bsm+m1f+m0f+self+red)
#define NCH 8

template <bool APPLY>
__global__ __launch_bounds__(256, 2) void k_gemm_mma(const float* __restrict__ bias,
                                                     const float* __restrict__ unc,
                                                     const float* __restrict__ r_anc,
                                                     const float* __restrict__ r_pos,
                                                     const float* __restrict__ r_neg) {
    extern __shared__ __align__(16) char smraw[];
    int Bl = blockIdx.x;
    if (!APPLY) {
        if (Bl < 8) {
            do_select(smraw, Bl, unc, r_anc, r_pos, r_neg);
            return;
        }
        Bl -= 8;
    }
    const int bx = Bl & 127, mb = (Bl >> 7) & 1, bb = Bl >> 8;

    float* ext = (float*)smraw + OFF_EXT;
    float* bsm = ext;
    float* m1f = ext + 128;
    float* m0f = ext + 256;
    float* self = ext + 384;   // [128] selection flags (APPLY only)
    float* red = ext + 512;    // [2][128][4] = 1024 floats -> ends at 1536
    const uint32_t sb = (uint32_t)__cvta_generic_to_shared(smraw);

    const int tid = threadIdx.x, lane = tid & 31, wid = tid >> 5;
    const int warp_m = wid >> 2, warp_n = wid & 3;
    const int nb = bx * 128;

    if (tid < 128) bsm[tid] = bias[mb * 128 + tid];
    if (APPLY && tid < 128) {
        m1f[tid] = (float)g_m1[bb * HW + nb + tid];
        m0f[tid] = (float)g_m0[bb * HW + nb + tid];
        self[tid] = (float)g_sel[bb * HW + nb + tid];
    }

    const __nv_bfloat16* WH = APPLY ? g_w2h : g_w1h;
    const __nv_bfloat16* WL = APPLY ? g_w2l : g_w1l;
    const __nv_bfloat16* BH = (APPLY ? g_xh : g_fh) + (size_t)bb * HW * 256;
    const __nv_bfloat16* BL = (APPLY ? g_xl : g_fl) + (size_t)bb * HW * 256;

    float acc[4][4][4];
#pragma unroll
    for (int i = 0; i < 4; i++)
#pragma unroll
        for (int j = 0; j < 4; j++)
#pragma unroll
            for (int k = 0; k < 4; k++) acc[i][j][k] = 0.f;

    const int rA = lane >> 2, cA = lane & 3;
    const int aLane = (warp_m * 64 + (lane & 15)) * 80 + (lane >> 4) * 16;
    const int bLane = (warp_n * 32 + (lane & 7)) * 80 + ((lane >> 3) & 1) * 16;

    auto issue = [&](int kc, int stage) {
        const int d0 = kc * 32;
        uint32_t base = sb + stage * STAGEW * 4;
#pragma unroll
        for (int it = 0; it < 2; it++) {
            int lin = it * 256 + tid;
            int r = lin >> 2, c = lin & 3;
            uint32_t doff = (r * ROWW + c * 4) * 4;
            size_t aoff = ((size_t)(mb * 128 + r) * 256 + d0 + c * 8);
            size_t boff = ((size_t)(nb + r) * 256 + d0 + c * 8);
            CP16(base + doff, (const char*)WH + aoff * 2);
            CP16(base + MATW * 4 + doff, (const char*)WL + aoff * 2);
            CP16(base + 2 * MATW * 4 + doff, (const char*)BH + boff * 2);
            CP16(base + 3 * MATW * 4 + doff, (const char*)BL + boff * 2);
        }
        CP_COMMIT();
    };

    issue(0, 0);
    issue(1, 1);

#pragma unroll 1
    for (int kc = 0; kc < NCH; kc++) {
        const int stage = kc & 1;
        if (kc < NCH - 1) CP_WAIT1(); else CP_WAIT0();
        __syncthreads();
        uint32_t AhB = sb + stage * STAGEW * 4;
        uint32_t AlB = AhB + MATW * 4;
        uint32_t BhB = AlB + MATW * 4;
        uint32_t BlB = BhB + MATW * 4;
#pragma unroll
        for (int kt = 0; kt < 2; kt++) {
            uint32_t Afh[4][4], Afl[4][4];
#pragma unroll
            for (int mt = 0; mt < 4; mt++) {
                ldsm_x4(Afh[mt], AhB + aLane + mt * 16 * 80 + kt * 32);
                ldsm_x4(Afl[mt], AlB + aLane + mt * 16 * 80 + kt * 32);
            }
#pragma unroll
            for (int nt = 0; nt < 4; nt++) {
                uint32_t bh0, bh1, bl0, bl1;
                ldsm_x2(bh0, bh1, BhB + bLane + nt * 8 * 80 + kt * 32);
                ldsm_x2(bl0, bl1, BlB + bLane + nt * 8 * 80 + kt * 32);
#pragma unroll
                for (int mt = 0; mt < 4; mt++) {
                    mma16816(acc[mt][nt], Afh[mt], bh0, bh1);
                    mma16816(acc[mt][nt], Afh[mt], bl0, bl1);
                    mma16816(acc[mt][nt], Afl[mt], bh0, bh1);
                }
            }
        }
        __syncthreads();
        if (kc + 2 < NCH) issue(kc + 2, stage);
    }

    float* outb = (APPLY ? g_proj : g_x) + (size_t)bb * HW * 256;
#pragma unroll
    for (int mt = 0; mt < 4; mt++) {
#pragma unroll
        for (int h = 0; h < 2; h++) {
            int e_local = warp_m * 64 + mt * 16 + rA + h * 8;
            int e = mb * 128 + e_local;
            float bv = bsm[e_local];
            float s0 = 0.f, s1 = 0.f;
#pragma unroll
            for (int nt = 0; nt < 4; nt++) {
                int nc = warp_n * 32 + nt * 8 + cA * 2;
                float v0 = acc[mt][nt][h * 2 + 0] + bv;
                float v1 = acc[mt][nt][h * 2 + 1] + bv;
                if (!APPLY) {
                    outb[(size_t)(nb + nc) * 256 + e] = v0;
                    outb[(size_t)(nb + nc + 1) * 256 + e] = v1;
                    s0 += v0 + v1;
                    s1 += v0 * v0 + v1 * v1;
                } else {
                    if (self[nc] != 0.f) outb[(size_t)(nb + nc) * 256 + e] = v0;
                    if (self[nc + 1] != 0.f) outb[(size_t)(nb + nc + 1) * 256 + e] = v1;
                    s0 += m1f[nc] * v0 + m1f[nc + 1] * v1;
                    s1 += m0f[nc] * v0 + m0f[nc + 1] * v1;
                }
            }
            s0 += __shfl_down_sync(0xffffffffu, s0, 1, 4);
            s0 += __shfl_down_sync(0xffffffffu, s0, 2, 4);
            s1 += __shfl_down_sync(0xffffffffu, s1, 1, 4);
            s1 += __shfl_down_sync(0xffffffffu, s1, 2, 4);
            if (cA == 0) {
                red[(0 * 128 + e_local) * 4 + warp_n] = s0;
                red[(1 * 128 + e_local) * 4 + warp_n] = s1;
            }
        }
    }
    __syncthreads();
    {
        int q = tid >> 7, e_local = tid & 127;
        int e = mb * 128 + e_local;
        const float* r4 = &red[(q * 128 + e_local) * 4];
        float s = r4[0] + r4[1] + r4[2] + r4[3];
        if (!APPLY) {
            if (q == 0)
                g_ps[(size_t)e * 512 + bb * 128 + bx] = s;
            else
                g_pq[(size_t)e * 512 + bb * 128 + bx] = s;
        } else {
            if (q == 0)
                g_pfg[(size_t)(bb * Dm + e) * NBLK + bx] = s;
            else
                g_pbg[(size_t)(bb * Dm + e) * NBLK + bx] = s;
        }
    }
}

// ---------------- finalize BN stats ------------------------------------------
__global__ __launch_bounds__(128) void k_finstats(const float* __restrict__ gamma,
                                                  const float* __restrict__ beta) {
    __shared__ float shs[4], shq[4];
    int e = blockIdx.x, t = threadIdx.x, lane = t & 31, wp = t >> 5;
    float s = 0.f, q = 0.f;
    for (int i = t; i < 512; i += 128) {
        s += g_ps[e * 512 + i];
        q += g_pq[e * 512 + i];
    }
#pragma unroll
    for (int off = 16; off; off >>= 1) {
        s += __shfl_down_sync(0xffffffffu, s, off);
        q += __shfl_down_sync(0xffffffffu, q, off);
    }
    if (lane == 0) {
        shs[wp] = s;
        shq[wp] = q;
    }
    __syncthreads();
    if (t == 0) {
        float ts = shs[0] + shs[1] + shs[2] + shs[3];
        float tq = shq[0] + shq[1] + shq[2] + shq[3];
        const float inv_n = 1.f / (float)(Bm * HW);
        float mean = ts * inv_n;
        float var = fmaxf(tq * inv_n - mean * mean, 0.f);
        float sc = gamma[e] / sqrtf(var + 1e-5f);
        g_s[e] = sc;
        g_c[e] = beta[e] - mean * sc;
    }
}

// ---------------- tail: finproto (blocks 0-1023) + dot (blocks 1024-1055) -----
__global__ __launch_bounds__(256) void k_tail() {
    int blk = blockIdx.x;
    int tid = threadIdx.x, w = tid >> 5, l = tid & 31;
    if (blk < 1024) {  // finproto: e = blk & 255, b = blk >> 8
        __shared__ float shf[8], shb[8];
        int e = blk & 255, b = blk >> 8;
        float f = 0.f, g = 0.f;
        if (tid < NBLK) {
            f = g_pfg[(b * Dm + e) * NBLK + tid];
            g = g_pbg[(b * Dm + e) * NBLK + tid];
        }
#pragma unroll
        for (int off = 16; off; off >>= 1) {
            f += __shfl_down_sync(0xffffffffu, f, off);
            g += __shfl_down_sync(0xffffffffu, g, off);
        }
        if (l == 0) {
            shf[w] = f;
            shb[w] = g;
        }
        __syncthreads();
        if (tid == 0) {
            float tf = 0.f, tb = 0.f;
#pragma unroll
            for (int ww = 0; ww < 8; ww++) {
                tf += shf[ww];
                tb += shb[ww];
            }
            g_mfg[b * Dm + e] = tf;
            g_mbg[b * Dm + e] = tb;
        }
        return;
    }
    // dot phase
    __shared__ float qs[32 * 257];
    __shared__ float vbuf[8][264];
    __shared__ float warpP[8][33];
    int db = blk - 1024;
    int task = db >> 2, sg = db & 3;
    int b = task >> 1;
    const float* projb = g_proj + (size_t)b * HW * 256;

    for (int q = 0; q < 4; q++) {
        int a = w * 4 + q;
        const float* src = projb + (size_t)g_aidx[task * 32 + a] * 256;
        float v[8], ss = 0.f;
#pragma unroll
        for (int cc = 0; cc < 8; cc++) {
            v[cc] = src[l + 32 * cc];
            ss = fmaf(v[cc], v[cc], ss);
        }
#pragma unroll
        for (int off = 16; off; off >>= 1) ss += __shfl_xor_sync(0xffffffffu, ss, off);
        float sc = 1.f / fmaxf(sqrtf(ss), 1e-12f);
#pragma unroll
        for (int cc = 0; cc < 8; cc++) qs[a * 257 + l + 32 * cc] = v[cc] * sc;
    }
    __syncthreads();

    float accv = 0.f;
    for (int q = 0; q < 4; q++) {
        int s = sg * 32 + w + q * 8;
        bool isP = s < 64;
        int si = isP ? s : s - 64;
        float fl = isP ? g_pflag[task * 64 + si] : g_nflag[task * 64 + si];
        if (fl != 0.f) {
            int idx = isP ? g_pidx[task * 64 + si] : g_nidx[task * 64 + si];
            const float* src = projb + (size_t)idx * 256;
            float v[8], ss = 0.f;
#pragma unroll
            for (int cc = 0; cc < 8; cc++) {
                v[cc] = src[l + 32 * cc];
                ss = fmaf(v[cc], v[cc], ss);
            }
#pragma unroll
            for (int off = 16; off; off >>= 1) ss += __shfl_xor_sync(0xffffffffu, ss, off);
            float sc = 1.f / fmaxf(sqrtf(ss), 1e-12f);
#pragma unroll
            for (int cc = 0; cc < 8; cc++) vbuf[w][l + 32 * cc] = v[cc] * sc;
            __syncwarp();
            float dot = 0.f;
            const float* qrow = &qs[l * 257];
#pragma unroll 8
            for (int d = 0; d < 256; d++) dot = fmaf(qrow[d], vbuf[w][d], dot);
            accv += expf(dot * 10.f);
            __syncwarp();
        }
    }
    warpP[w][l] = accv;
    __syncthreads();
    if (w == 0) {
        float p = 0.f;
#pragma unroll
        for (int ww = 0; ww < 8; ww++) p += warpP[ww][l];
        g_dacc[(task * 4 + sg) * 32 + l] = p;
    }
}

// ---------------- final: pair finalize + local + global loss -----------------
__global__ __launch_bounds__(256) void k_final(float* __restrict__ out, int out_size) {
    __shared__ float scratch[34];
    __shared__ float qf[4][257], qb[4][257];
    __shared__ float cf[4], cb[4];
    __shared__ float pfv[4], pbv[4], nfv[4], nbv[4];
    __shared__ float sbl[8];
    __shared__ int sinc[8];
    int tid = threadIdx.x;

    {
        int task = tid >> 5, l = tid & 31;
        float p = g_dacc[(task * 4 + 0) * 32 + l] + g_dacc[(task * 4 + 1) * 32 + l];
        float n = g_dacc[(task * 4 + 2) * 32 + l] + g_dacc[(task * 4 + 3) * 32 + l];
        bool inc = (g_cA[task] >= 1) && (g_cB[task] >= 1);
        if (!inc) p += 1.f;
        float per = -logf(p / (p + n + 1e-8f));
        float af = g_aflag[task * 32 + l];
        float ws = per * af, as = af;
#pragma unroll
        for (int off = 16; off; off >>= 1) {
            ws += __shfl_down_sync(0xffffffffu, ws, off);
            as += __shfl_down_sync(0xffffffffu, as, off);
        }
        if (l == 0) {
            sbl[task] = inc ? (ws / fmaxf(as, 1.f)) : 0.f;
            sinc[task] = inc ? 1 : 0;
        }
    }
    __syncthreads();

    for (int b = 0; b < 4; b++) {
        float c1 = 0.f, c0 = 0.f;
        for (int i = tid; i < HW; i += 256) {
            c1 += (float)g_m1[b * HW + i];
            c0 += (float)g_m0[b * HW + i];
        }
        float s1 = blk_sum(scratch, c1, tid);
        float s0 = blk_sum(scratch, c0, tid);
        if (tid == 0) { cf[b] = s1; cb[b] = s0; }
    }
    __syncthreads();

    for (int b = 0; b < 4; b++) {
        float mf = g_mfg[b * Dm + tid] / fmaxf(cf[b], 1.f);
        float mb_ = g_mbg[b * Dm + tid] / fmaxf(cb[b], 1.f);
        float ssf = blk_sum(scratch, mf * mf, tid);
        qf[b][tid] = mf / fmaxf(sqrtf(ssf), 1e-12f);
        float ssb = blk_sum(scratch, mb_ * mb_, tid);
        qb[b][tid] = mb_ / fmaxf(sqrtf(ssb), 1e-12f);
    }
    __syncthreads();

    for (int b = 0; b < 4; b++) {
        float d1 = blk_sum(scratch, qf[b][tid] * qf[b][tid], tid);
        float d2 = blk_sum(scratch, qb[b][tid] * qb[b][tid], tid);
        if (tid == 0) {
            pfv[b] = expf(d1 * 10.f);
            pbv[b] = expf(d2 * 10.f);
            nfv[b] = 0.f;
            nbv[b] = 0.f;
        }
        __syncthreads();
    }
    for (int b = 0; b < 4; b++) {
        for (int j = 0; j <= b; j++) {
            float dqbqf = blk_sum(scratch, qb[j][tid] * qf[b][tid], tid);
            float dqfqb = blk_sum(scratch, qf[j][tid] * qb[b][tid], tid);
            if (tid == 0) {
                bool vgj = (cf[j] >= 1.f) && (cb[j] >= 1.f);
                if (vgj) {
                    nfv[b] += expf(dqbqf * 10.f);
                    nbv[b] += expf(dqfqb * 10.f);
                }
            }
            __syncthreads();
        }
    }

    if (tid == 0) {
        float lsum = 0.f;
        int icnt = 0;
        for (int t = 0; t < 8; t++) {
            lsum += sbl[t];
            icnt += sinc[t];
        }
        float l_local = lsum / (float)max(icnt, 1);
        float gs = 0.f;
        int vcnt = 0;
        for (int b = 0; b < 4; b++) {
            bool vg = (cf[b] >= 1.f) && (cb[b] >= 1.f);
            if (vg) {
                float lg = -logf(pfv[b] / (pfv[b] + nfv[b] + 1e-8f)) -
                           logf(pbv[b] / (pbv[b] + nbv[b] + 1e-8f));
                gs += lg;
                vcnt++;
            }
        }
        float l_global = gs / (float)max(vcnt, 1);
        if (out_size > 0) out[0] = l_local + 0.5f * l_global;
        if (out_size > 1) out[1] = l_local;
        if (out_size > 2) out[2] = l_global;
    }
}

// ---------------- launch ------------------------------------------------------
extern "C" void kernel_launch(void* const* d_in, const int* in_sizes, int n_in, void* d_out,
                              int out_size) {
    const float* feat = (const float*)d_in[0];
    const int* labels = (const int*)d_in[1];
    const float* prob_ori = (const float*)d_in[2];
    const float* prob_aug = (const float*)d_in[3];
    const float* unc = (const float*)d_in[4];
    const float* r_anc = (const float*)d_in[5];
    const float* r_pos = (const float*)d_in[6];
    const float* r_neg = (const float*)d_in[7];
    const float* w1 = (const float*)d_in[8];
    const float* b1 = (const float*)d_in[9];
    const float* gamma = (const float*)d_in[10];
    const float* beta = (const float*)d_in[11];
    const float* w2 = (const float*)d_in[12];
    const float* b2 = (const float*)d_in[13];

    cudaFuncSetAttribute(k_gemm_mma<false>, cudaFuncAttributeMaxDynamicSharedMemorySize,
                         GEMM_SMEM);
    cudaFuncSetAttribute(k_gemm_mma<true>, cudaFuncAttributeMaxDynamicSharedMemorySize,
                         GEMM_SMEM);

    k_pre<<<384 + 4096, 256>>>(prob_ori, prob_aug, unc, labels, w1, w2, feat);
    k_gemm_mma<false><<<8 + NBLK * 2 * Bm, 256, GEMM_SMEM>>>(b1, unc, r_anc, r_pos, r_neg);
    k_finstats<<<Dm, 128>>>(gamma, beta);
    k_bnsplit<<<Bm * HW / 16, 256>>>();
    k_gemm_mma<true><<<NBLK * 2 * Bm, 256, GEMM_SMEM>>>(b2, nullptr, nullptr, nullptr, nullptr);
    k_tail<<<1024 + 32, 256>>>();
    k_final<<<1, 256>>>((float*)d_out, out_size);
}

// round 17
// speedup vs baseline: 1.5399x; 1.5399x over previous
#include <cuda_runtime.h>
#include <cuda_bf16.h>
#include <float.h>
#include <math.h>
#include <stdint.h>

#define HW 16384
#define Dm 256
#define Bm 4
#define NBLK 128

// ---------------- scratch ----------------------------------------------------
__device__ float g_x[Bm * HW * Dm];
__device__ float g_proj[Bm * HW * Dm];
__device__ __nv_bfloat16 g_fh[Bm * HW * Dm];
__device__ __nv_bfloat16 g_fl[Bm * HW * Dm];
__device__ __nv_bfloat16 g_xh[Bm * HW * Dm];
__device__ __nv_bfloat16 g_xl[Bm * HW * Dm];
__device__ __nv_bfloat16 g_w1h[Dm * Dm], g_w1l[Dm * Dm];
__device__ __nv_bfloat16 g_w2h[Dm * Dm], g_w2l[Dm * Dm];
__device__ float g_s[Dm];
__device__ float g_c[Dm];
__device__ unsigned char g_m1[Bm * HW];
__device__ unsigned char g_m0[Bm * HW];
__device__ unsigned char g_sel[Bm * HW];
__device__ float g_ps[Dm * 512];
__device__ float g_pq[Dm * 512];
__device__ float g_pfg[Bm * Dm * NBLK];
__device__ float g_pbg[Bm * Dm * NBLK];
__device__ float g_mfg[Bm * Dm];
__device__ float g_mbg[Bm * Dm];
// selection outputs
__device__ int g_aidx[8 * 32];
__device__ float g_aflag[8 * 32];
__device__ int g_pidx[8 * 64];
__device__ float g_pflag[8 * 64];
__device__ int g_nidx[8 * 64];
__device__ float g_nflag[8 * 64];
__device__ int g_cA[8], g_cB[8];
__device__ float g_dacc[8 * 4 * 32];

// ---------------- block reduction --------------------------------------------
__device__ __forceinline__ float blk_sum(volatile float* scratch, float v, int tid) {
    int lane = tid & 31, w = tid >> 5;
#pragma unroll
    for (int off = 16; off; off >>= 1) v += __shfl_down_sync(0xffffffffu, v, off);
    if (lane == 0) scratch[w] = v;
    __syncthreads();
    if (w == 0) {
        v = (lane < 8) ? scratch[lane] : 0.f;
#pragma unroll
        for (int off = 4; off; off >>= 1) v += __shfl_down_sync(0xffffffffu, v, off);
        if (lane == 0) scratch[32] = v;
    }
    __syncthreads();
    return scratch[32];
}

// ---------------- bf16 hi/lo split -------------------------------------------
__device__ __forceinline__ void split2(float a, float b, uint32_t& h, uint32_t& l) {
    __nv_bfloat16 ah = __float2bfloat16_rn(a), bh = __float2bfloat16_rn(b);
    float ar = a - __bfloat162float(ah), br = b - __bfloat162float(bh);
    __nv_bfloat16 al = __float2bfloat16_rn(ar), bl = __float2bfloat16_rn(br);
    h = (uint32_t)*(unsigned short*)&ah | ((uint32_t)*(unsigned short*)&bh << 16);
    l = (uint32_t)*(unsigned short*)&al | ((uint32_t)*(unsigned short*)&bl << 16);
}

__device__ __forceinline__ void mma16816(float* c, const uint32_t* a, uint32_t b0, uint32_t b1) {
    asm volatile(
        "mma.sync.aligned.m16n8k16.row.col.f32.bf16.bf16.f32 "
        "{%0,%1,%2,%3}, {%4,%5,%6,%7}, {%8,%9}, {%0,%1,%2,%3};"
        : "+f"(c[0]), "+f"(c[1]), "+f"(c[2]), "+f"(c[3])
        : "r"(a[0]), "r"(a[1]), "r"(a[2]), "r"(a[3]), "r"(b0), "r"(b1));
}

__device__ __forceinline__ void ldsm_x4(uint32_t* r, uint32_t addr) {
    asm volatile("ldmatrix.sync.aligned.m8n8.x4.shared.b16 {%0,%1,%2,%3}, [%4];"
                 : "=r"(r[0]), "=r"(r[1]), "=r"(r[2]), "=r"(r[3])
                 : "r"(addr));
}
__device__ __forceinline__ void ldsm_x2(uint32_t& r0, uint32_t& r1, uint32_t addr) {
    asm volatile("ldmatrix.sync.aligned.m8n8.x2.shared.b16 {%0,%1}, [%2];"
                 : "=r"(r0), "=r"(r1)
                 : "r"(addr));
}

#define CP16(dst_u32, src_ptr) \
    asm volatile("cp.async.cg.shared.global [%0], [%1], 16;" ::"r"(dst_u32), "l"(src_ptr))
#define CP_COMMIT() asm volatile("cp.async.commit_group;" ::: "memory")
#define CP_WAIT1() asm volatile("cp.async.wait_group 1;" ::: "memory")
#define CP_WAIT0() asm volatile("cp.async.wait_group 0;" ::: "memory")

// ---------------- fused prologue: masks(+sel clear) + splitw + split_feat -----
__global__ __launch_bounds__(256) void k_pre(const float* __restrict__ prob_ori,
                                             const float* __restrict__ prob_aug,
                                             const float* __restrict__ unc,
                                             const int* __restrict__ labels,
                                             const float* __restrict__ w1,
                                             const float* __restrict__ w2,
                                             const float* __restrict__ feat) {
    __shared__ float tile[64 * 65];
    int blk = blockIdx.x;
    int tid = threadIdx.x;
    if (blk < 256) {  // masks + sel clear
        int idx = blk * 256 + tid;
        int b = idx >> 14;
        int hw = idx & (HW - 1);
        const float* po = prob_ori + (size_t)b * 2 * HW;
        const float* pa = prob_aug + (size_t)b * 2 * HW;
        int io = po[HW + hw] > po[hw];
        int ia = pa[HW + hw] > pa[hw];
        bool rel = (io == ia);
        bool diff = unc[idx] > 0.5f;
        int lab = labels[idx];
        bool valid = rel && diff;
        g_m1[idx] = (unsigned char)(valid && lab == 1);
        g_m0[idx] = (unsigned char)(valid && lab == 0);
        g_sel[idx] = 0;
        return;
    }
    if (blk < 384) {  // splitw
        int lin = (blk - 256) * 256 + tid;
#pragma unroll
        for (int s = 0; s < 2; s++) {
            const float* w = s ? w2 : w1;
            uint32_t* oh = (uint32_t*)(s ? g_w2h : g_w1h);
            uint32_t* ol = (uint32_t*)(s ? g_w2l : g_w1l);
            float a = w[2 * lin], b = w[2 * lin + 1];
            uint32_t h, l;
            split2(a, b, h, l);
            oh[lin] = h;
            ol[lin] = l;
        }
        return;
    }
    // split_feat
    int fb = blk - 384;
    int bxi = fb & 255, bzi = fb >> 8;
    int n0 = bxi * 64;
    int d0 = (bzi & 3) * 64;
    int b = bzi >> 2;
    const float* src = feat + ((size_t)b * Dm + d0) * HW + n0;
#pragma unroll
    for (int it = 0; it < 4; it++) {
        int lin = it * 256 + tid;
        int r = lin >> 4, c4 = lin & 15;
        float4 v = *(const float4*)(src + (size_t)r * HW + c4 * 4);
        tile[r * 65 + c4 * 4 + 0] = v.x;
        tile[r * 65 + c4 * 4 + 1] = v.y;
        tile[r * 65 + c4 * 4 + 2] = v.z;
        tile[r * 65 + c4 * 4 + 3] = v.w;
    }
    __syncthreads();
    uint32_t* oh = (uint32_t*)g_fh;
    uint32_t* ol = (uint32_t*)g_fl;
#pragma unroll
    for (int it = 0; it < 8; it++) {
        int lin = it * 256 + tid;
        int n = lin >> 5, c = lin & 31;
        float v0 = tile[(2 * c) * 65 + n];
        float v1 = tile[(2 * c + 1) * 65 + n];
        uint32_t h, l;
        split2(v0, v1, h, l);
        size_t o = (((size_t)b * HW + n0 + n) * 256 + d0) / 2 + c;
        oh[o] = h;
        ol[o] = l;
    }
}

// ---------------- bn+relu+split (2 rows/warp, MLP=4, fully coalesced) ---------
__global__ __launch_bounds__(256) void k_bnsplit() {
    __shared__ float scs[256], scc[256];
    int tid = threadIdx.x, lane = tid & 31, w = tid >> 5;
    scs[tid] = g_s[tid];
    scc[tid] = g_c[tid];
    __syncthreads();
    size_t row0 = (size_t)blockIdx.x * 16 + w * 2;
    const float* s0 = g_x + row0 * 256;
    const float* s1 = s0 + 256;
    // 4 independent, fully-coalesced loads (each instr covers 512B contiguous)
    float4 a0 = *(const float4*)(s0 + lane * 4);
    float4 a1 = *(const float4*)(s0 + 128 + lane * 4);
    float4 b0 = *(const float4*)(s1 + lane * 4);
    float4 b1 = *(const float4*)(s1 + 128 + lane * 4);
    int dA = lane * 4, dB = 128 + lane * 4;
    float v0[8] = {a0.x, a0.y, a0.z, a0.w, a1.x, a1.y, a1.z, a1.w};
    float v1[8] = {b0.x, b0.y, b0.z, b0.w, b1.x, b1.y, b1.z, b1.w};
#pragma unroll
    for (int j = 0; j < 4; j++) {
        v0[j] = fmaxf(fmaf(scs[dA + j], v0[j], scc[dA + j]), 0.f);
        v0[4 + j] = fmaxf(fmaf(scs[dB + j], v0[4 + j], scc[dB + j]), 0.f);
        v1[j] = fmaxf(fmaf(scs[dA + j], v1[j], scc[dA + j]), 0.f);
        v1[4 + j] = fmaxf(fmaf(scs[dB + j], v1[4 + j], scc[dB + j]), 0.f);
    }
    uint32_t H0[4], L0[4], H1[4], L1[4];
#pragma unroll
    for (int j = 0; j < 4; j++) {
        split2(v0[2 * j], v0[2 * j + 1], H0[j], L0[j]);
        split2(v1[2 * j], v1[2 * j + 1], H1[j], L1[j]);
    }
    uint32_t* xh = (uint32_t*)g_xh;
    uint32_t* xl = (uint32_t*)g_xl;
    size_t oA0 = row0 * 128 + lane * 2;        // row0, d [lane*4, +4)
    size_t oB0 = row0 * 128 + 64 + lane * 2;   // row0, d [128+lane*4, +4)
    size_t oA1 = oA0 + 128, oB1 = oB0 + 128;   // row1
    *(uint2*)&xh[oA0] = make_uint2(H0[0], H0[1]);
    *(uint2*)&xh[oB0] = make_uint2(H0[2], H0[3]);
    *(uint2*)&xh[oA1] = make_uint2(H1[0], H1[1]);
    *(uint2*)&xh[oB1] = make_uint2(H1[2], H1[3]);
    *(uint2*)&xl[oA0] = make_uint2(L0[0], L0[1]);
    *(uint2*)&xl[oB0] = make_uint2(L0[2], L0[3]);
    *(uint2*)&xl[oA1] = make_uint2(L1[0], L1[1]);
    *(uint2*)&xl[oB1] = make_uint2(L1[2], L1[3]);
}

// ---------------- selection (smem struct + helpers) ---------------------------
struct PairS {
    unsigned short listA[HW];
    unsigned short listN[HW];
    unsigned long long sbuf[512];
    int hist[256];
    float red[34];
    int redi[34];
    int cidx[128];
    float cflag[128];
    int cntA, cntN, coll, bstar;
    float bestv;
    int besti;
};

__device__ __forceinline__ void pair_argmax(PairS* S, float v, int i, int tid) {
    int lane = tid & 31, w = tid >> 5;
#pragma unroll
    for (int off = 16; off; off >>= 1) {
        float ov = __shfl_down_sync(0xffffffffu, v, off);
        int oi = __shfl_down_sync(0xffffffffu, i, off);
        if (ov > v || (ov == v && oi < i)) { v = ov; i = oi; }
    }
    if (lane == 0) { S->red[w] = v; S->redi[w] = i; }
    __syncthreads();
    if (w == 0) {
        v = (lane < 8) ? S->red[lane] : -FLT_MAX;
        i = (lane < 8) ? S->redi[lane] : 0x7FFFFFFF;
#pragma unroll
        for (int off = 4; off; off >>= 1) {
            float ov = __shfl_down_sync(0xffffffffu, v, off);
            int oi = __shfl_down_sync(0xffffffffu, i, off);
            if (ov > v || (ov == v && oi < i)) { v = ov; i = oi; }
        }
        if (lane == 0) { S->bestv = v; S->besti = i; }
    }
    __syncthreads();
}

__device__ void select_topk(PairS* S, const unsigned short* list, int cnt,
                            const float* __restrict__ key, int K, int* oidx, float* oflag,
                            int tid) {
    float lastv = FLT_MAX;
    int lasti = -1;
    for (int kk = 0; kk < K; kk++) {
        float bv = -FLT_MAX;
        int bi = 0x7FFFFFFF;
        for (int ii = tid; ii < cnt; ii += 256) {
            int idx = list[ii];
            float v = key[idx];
            if (v < lastv || (v == lastv && idx > lasti)) {
                if (v > bv || (v == bv && idx < bi)) { bv = v; bi = idx; }
            }
        }
        pair_argmax(S, bv, bi, tid);
        float gbv = S->bestv;
        int gbi = S->besti;
        if (gbv > -FLT_MAX) {
            lastv = gbv;
            lasti = gbi;
            if (tid == 0) { oidx[kk] = gbi; oflag[kk] = 1.f; }
        } else {
            lastv = -FLT_MAX;
            lasti = 0x7FFFFFFF;
            if (tid == 0) { oidx[kk] = 0; oflag[kk] = 0.f; }
        }
        __syncthreads();
    }
}

__device__ void bitonic_desc(PairS* S, int n, int tid) {
    for (int k = 2; k <= n; k <<= 1)
        for (int j = k >> 1; j > 0; j >>= 1) {
            for (int t = tid; t < n; t += 256) {
                int ixj = t ^ j;
                if (ixj > t) {
                    unsigned long long x = S->sbuf[t], y = S->sbuf[ixj];
                    bool desc = ((t & k) == 0);
                    if (desc ? (x < y) : (x > y)) {
                        S->sbuf[t] = y;
                        S->sbuf[ixj] = x;
                    }
                }
            }
            __syncthreads();
        }
}

__device__ void radix_select(PairS* S, const unsigned short* list, int cnt,
                             const float* __restrict__ key, int K, int* oidx, float* oflag,
                             int tid) {
    int target = min(K, cnt);
    if (target == 0) {
        for (int kk = tid; kk < K; kk += 256) { oidx[kk] = 0; oflag[kk] = 0.f; }
        __syncthreads();
        return;
    }
    S->hist[tid] = 0;
    __syncthreads();
    for (int ii = tid; ii < cnt; ii += 256) {
        float r = key[list[ii]];
        int b = (int)(r * 256.f);
        b = b < 0 ? 0 : (b > 255 ? 255 : b);
        atomicAdd(&S->hist[b], 1);
    }
    __syncthreads();
    if (tid == 0) {
        int acc = 0, bs = 0;
        for (int b = 255; b >= 0; b--) {
            acc += S->hist[b];
            if (acc >= target) { bs = b; break; }
        }
        S->bstar = bs;
        S->coll = 0;
    }
    __syncthreads();
    int bstar = S->bstar;
    for (int ii = tid; ii < cnt; ii += 256) {
        int idx = list[ii];
        float r = key[idx];
        int b = (int)(r * 256.f);
        b = b < 0 ? 0 : (b > 255 ? 255 : b);
        if (b >= bstar) {
            int p = atomicAdd(&S->coll, 1);
            if (p < 512)
                S->sbuf[p] = ((unsigned long long)__float_as_uint(r) << 32) |
                             (unsigned long long)(unsigned int)(~(unsigned int)idx);
        }
    }
    __syncthreads();
    int coll = S->coll;
    if (coll > 512) {
        select_topk(S, list, cnt, key, K, oidx, oflag, tid);
        return;
    }
    int n = 1;
    while (n < coll) n <<= 1;
    for (int i = coll + tid; i < n; i += 256) S->sbuf[i] = 0ull;
    __syncthreads();
    bitonic_desc(S, n, tid);
    for (int kk = tid; kk < K; kk += 256) {
        if (kk < target) {
            oidx[kk] = (int)(~(unsigned int)(S->sbuf[kk] & 0xFFFFFFFFull));
            oflag[kk] = 1.f;
        } else {
            oidx[kk] = 0;
            oflag[kk] = 0.f;
        }
    }
    __syncthreads();
}

__device__ void hard_select(PairS* S, const float* __restrict__ ub, int* oidx, float* oflag,
                            int tid) {
    if (tid < 128) {
        unsigned long long kv;
        if (S->cflag[tid] != 0.f) {
            unsigned int u = __float_as_uint(ub[S->cidx[tid]]) + 1u;
            kv = ((unsigned long long)u << 32) |
                 (unsigned long long)(unsigned int)(~(unsigned int)tid);
        } else {
            kv = (unsigned long long)(unsigned int)(~(unsigned int)tid);
        }
        S->sbuf[tid] = kv;
    }
    __syncthreads();
    bitonic_desc(S, 128, tid);
    if (tid < 64) {
        int t = (int)((~(unsigned int)(S->sbuf[tid] & 0xFFFFFFFFull)) & 127u);
        oidx[tid] = S->cidx[t];
        oflag[tid] = S->cflag[t];
    }
    __syncthreads();
}

__device__ void do_select(char* smraw, int task, const float* unc, const float* r_anc,
                          const float* r_pos, const float* r_neg) {
    PairS* S = (PairS*)smraw;
    int b = task >> 1, c = task & 1;
    int tid = threadIdx.x;
    const unsigned char* am = (c == 0 ? g_m1 : g_m0) + b * HW;
    const unsigned char* nm = (c == 0 ? g_m0 : g_m1) + b * HW;

    if (tid == 0) { S->cntA = 0; S->cntN = 0; }
    __syncthreads();
    for (int i = tid; i < HW; i += 256) {
        if (am[i]) { int p = atomicAdd(&S->cntA, 1); S->listA[p] = (unsigned short)i; }
        if (nm[i]) { int p = atomicAdd(&S->cntN, 1); S->listN[p] = (unsigned short)i; }
    }
    __syncthreads();
    int cntA = S->cntA, cntN = S->cntN;

    const float* ra = r_anc + ((size_t)b * 2 + c) * HW;
    const float* rp = r_pos + ((size_t)b * 2 + c) * HW;
    const float* rn = r_neg + ((size_t)b * 2 + c) * HW;
    const float* ub = unc + (size_t)b * HW;

    radix_select(S, S->listA, cntA, ra, 32, g_aidx + task * 32, g_aflag + task * 32, tid);
    radix_select(S, S->listA, cntA, rp, 128, S->cidx, S->cflag, tid);
    hard_select(S, ub, g_pidx + task * 64, g_pflag + task * 64, tid);
    radix_select(S, S->listN, cntN, rn, 128, S->cidx, S->cflag, tid);
    hard_select(S, ub, g_nidx + task * 64, g_nflag + task * 64, tid);

    // mark selected rows for GEMM2's predicated g_proj writes (benign races: all write 1)
    if (tid < 32) g_sel[b * HW + g_aidx[task * 32 + tid]] = 1;
    if (tid < 64) g_sel[b * HW + g_pidx[task * 64 + tid]] = 1;
    if (tid < 64) g_sel[b * HW + g_nidx[task * 64 + tid]] = 1;

    if (tid == 0) {
        g_cA[task] = cntA;
        g_cB[task] = cntN;
    }
}

// ---------------- pure-bf16 HMMA GEMM ----------------------------------------
#define ROWW 20
#define MATW (128 * ROWW)
#define STAGEW (4 * MATW)
#define OFF_EXT (2 * STAGEW)
#define GEMM_SMEM ((OFF_EXT + 1536) * 4)  // 88064 bytes (bsm+m1f+m0f+self+red)
#define NCH 8

template <bool APPLY>
__global__ __launch_bounds__(256, 2) void k_gemm_mma(const float* __restrict__ bias,
                                                     const float* __restrict__ unc,
                                                     const float* __restrict__ r_anc,
                                                     const float* __restrict__ r_pos,
                                                     const float* __restrict__ r_neg) {
    extern __shared__ __align__(16) char smraw[];
    int Bl = blockIdx.x;
    if (!APPLY) {
        if (Bl < 8) {
            do_select(smraw, Bl, unc, r_anc, r_pos, r_neg);
            return;
        }
        Bl -= 8;
    }
    const int bx = Bl & 127, mb = (Bl >> 7) & 1, bb = Bl >> 8;

    float* ext = (float*)smraw + OFF_EXT;
    float* bsm = ext;
    float* m1f = ext + 128;
    float* m0f = ext + 256;
    float* self = ext + 384;   // [128] selection flags (APPLY only)
    float* red = ext + 512;    // [2][128][4] = 1024 floats -> ends at 1536
    const uint32_t sb = (uint32_t)__cvta_generic_to_shared(smraw);

    const int tid = threadIdx.x, lane = tid & 31, wid = tid >> 5;
    const int warp_m = wid >> 2, warp_n = wid & 3;
    const int nb = bx * 128;

    if (tid < 128) bsm[tid] = bias[mb * 128 + tid];
    if (APPLY && tid < 128) {
        m1f[tid] = (float)g_m1[bb * HW + nb + tid];
        m0f[tid] = (float)g_m0[bb * HW + nb + tid];
        self[tid] = (float)g_sel[bb * HW + nb + tid];
    }

    const __nv_bfloat16* WH = APPLY ? g_w2h : g_w1h;
    const __nv_bfloat16* WL = APPLY ? g_w2l : g_w1l;
    const __nv_bfloat16* BH = (APPLY ? g_xh : g_fh) + (size_t)bb * HW * 256;
    const __nv_bfloat16* BL = (APPLY ? g_xl : g_fl) + (size_t)bb * HW * 256;

    float acc[4][4][4];
#pragma unroll
    for (int i = 0; i < 4; i++)
#pragma unroll
        for (int j = 0; j < 4; j++)
#pragma unroll
            for (int k = 0; k < 4; k++) acc[i][j][k] = 0.f;

    const int rA = lane >> 2, cA = lane & 3;
    const int aLane = (warp_m * 64 + (lane & 15)) * 80 + (lane >> 4) * 16;
    const int bLane = (warp_n * 32 + (lane & 7)) * 80 + ((lane >> 3) & 1) * 16;

    auto issue = [&](int kc, int stage) {
        const int d0 = kc * 32;
        uint32_t base = sb + stage * STAGEW * 4;
#pragma unroll
        for (int it = 0; it < 2; it++) {
            int lin = it * 256 + tid;
            int r = lin >> 2, c = lin & 3;
            uint32_t doff = (r * ROWW + c * 4) * 4;
            size_t aoff = ((size_t)(mb * 128 + r) * 256 + d0 + c * 8);
            size_t boff = ((size_t)(nb + r) * 256 + d0 + c * 8);
            CP16(base + doff, (const char*)WH + aoff * 2);
            CP16(base + MATW * 4 + doff, (const char*)WL + aoff * 2);
            CP16(base + 2 * MATW * 4 + doff, (const char*)BH + boff * 2);
            CP16(base + 3 * MATW * 4 + doff, (const char*)BL + boff * 2);
        }
        CP_COMMIT();
    };

    issue(0, 0);
    issue(1, 1);

#pragma unroll 1
    for (int kc = 0; kc < NCH; kc++) {
        const int stage = kc & 1;
        if (kc < NCH - 1) CP_WAIT1(); else CP_WAIT0();
        __syncthreads();
        uint32_t AhB = sb + stage * STAGEW * 4;
        uint32_t AlB = AhB + MATW * 4;
        uint32_t BhB = AlB + MATW * 4;
        uint32_t BlB = BhB + MATW * 4;
#pragma unroll
        for (int kt = 0; kt < 2; kt++) {
            uint32_t Afh[4][4], Afl[4][4];
#pragma unroll
            for (int mt = 0; mt < 4; mt++) {
                ldsm_x4(Afh[mt], AhB + aLane + mt * 16 * 80 + kt * 32);
                ldsm_x4(Afl[mt], AlB + aLane + mt * 16 * 80 + kt * 32);
            }
#pragma unroll
            for (int nt = 0; nt < 4; nt++) {
                uint32_t bh0, bh1, bl0, bl1;
                ldsm_x2(bh0, bh1, BhB + bLane + nt * 8 * 80 + kt * 32);
                ldsm_x2(bl0, bl1, BlB + bLane + nt * 8 * 80 + kt * 32);
#pragma unroll
                for (int mt = 0; mt < 4; mt++) {
                    mma16816(acc[mt][nt], Afh[mt], bh0, bh1);
                    mma16816(acc[mt][nt], Afh[mt], bl0, bl1);
                    mma16816(acc[mt][nt], Afl[mt], bh0, bh1);
                }
            }
        }
        __syncthreads();
        if (kc + 2 < NCH) issue(kc + 2, stage);
    }

    float* outb = (APPLY ? g_proj : g_x) + (size_t)bb * HW * 256;
#pragma unroll
    for (int mt = 0; mt < 4; mt++) {
#pragma unroll
        for (int h = 0; h < 2; h++) {
            int e_local = warp_m * 64 + mt * 16 + rA + h * 8;
            int e = mb * 128 + e_local;
            float bv = bsm[e_local];
            float s0 = 0.f, s1 = 0.f;
#pragma unroll
            for (int nt = 0; nt < 4; nt++) {
                int nc = warp_n * 32 + nt * 8 + cA * 2;
                float v0 = acc[mt][nt][h * 2 + 0] + bv;
                float v1 = acc[mt][nt][h * 2 + 1] + bv;
                if (!APPLY) {
                    outb[(size_t)(nb + nc) * 256 + e] = v0;
                    outb[(size_t)(nb + nc + 1) * 256 + e] = v1;
                    s0 += v0 + v1;
                    s1 += v0 * v0 + v1 * v1;
                } else {
                    if (self[nc] != 0.f) outb[(size_t)(nb + nc) * 256 + e] = v0;
                    if (self[nc + 1] != 0.f) outb[(size_t)(nb + nc + 1) * 256 + e] = v1;
                    s0 += m1f[nc] * v0 + m1f[nc + 1] * v1;
                    s1 += m0f[nc] * v0 + m0f[nc + 1] * v1;
                }
            }
            s0 += __shfl_down_sync(0xffffffffu, s0, 1, 4);
            s0 += __shfl_down_sync(0xffffffffu, s0, 2, 4);
            s1 += __shfl_down_sync(0xffffffffu, s1, 1, 4);
            s1 += __shfl_down_sync(0xffffffffu, s1, 2, 4);
            if (cA == 0) {
                red[(0 * 128 + e_local) * 4 + warp_n] = s0;
                red[(1 * 128 + e_local) * 4 + warp_n] = s1;
            }
        }
    }
    __syncthreads();
    {
        int q = tid >> 7, e_local = tid & 127;
        int e = mb * 128 + e_local;
        const float* r4 = &red[(q * 128 + e_local) * 4];
        float s = r4[0] + r4[1] + r4[2] + r4[3];
        if (!APPLY) {
            if (q == 0)
                g_ps[(size_t)e * 512 + bb * 128 + bx] = s;
            else
                g_pq[(size_t)e * 512 + bb * 128 + bx] = s;
        } else {
            if (q == 0)
                g_pfg[(size_t)(bb * Dm + e) * NBLK + bx] = s;
            else
                g_pbg[(size_t)(bb * Dm + e) * NBLK + bx] = s;
        }
    }
}

// ---------------- finalize BN stats ------------------------------------------
__global__ __launch_bounds__(128) void k_finstats(const float* __restrict__ gamma,
                                                  const float* __restrict__ beta) {
    __shared__ float shs[4], shq[4];
    int e = blockIdx.x, t = threadIdx.x, lane = t & 31, wp = t >> 5;
    float s = 0.f, q = 0.f;
    for (int i = t; i < 512; i += 128) {
        s += g_ps[e * 512 + i];
        q += g_pq[e * 512 + i];
    }
#pragma unroll
    for (int off = 16; off; off >>= 1) {
        s += __shfl_down_sync(0xffffffffu, s, off);
        q += __shfl_down_sync(0xffffffffu, q, off);
    }
    if (lane == 0) {
        shs[wp] = s;
        shq[wp] = q;
    }
    __syncthreads();
    if (t == 0) {
        float ts = shs[0] + shs[1] + shs[2] + shs[3];
        float tq = shq[0] + shq[1] + shq[2] + shq[3];
        const float inv_n = 1.f / (float)(Bm * HW);
        float mean = ts * inv_n;
        float var = fmaxf(tq * inv_n - mean * mean, 0.f);
        float sc = gamma[e] / sqrtf(var + 1e-5f);
        g_s[e] = sc;
        g_c[e] = beta[e] - mean * sc;
    }
}

// ---------------- tail: finproto (blocks 0-1023) + dot (blocks 1024-1055) -----
__global__ __launch_bounds__(256) void k_tail() {
    int blk = blockIdx.x;
    int tid = threadIdx.x, w = tid >> 5, l = tid & 31;
    if (blk < 1024) {  // finproto: e = blk & 255, b = blk >> 8
        __shared__ float shf[8], shb[8];
        int e = blk & 255, b = blk >> 8;
        float f = 0.f, g = 0.f;
        if (tid < NBLK) {
            f = g_pfg[(b * Dm + e) * NBLK + tid];
            g = g_pbg[(b * Dm + e) * NBLK + tid];
        }
#pragma unroll
        for (int off = 16; off; off >>= 1) {
            f += __shfl_down_sync(0xffffffffu, f, off);
            g += __shfl_down_sync(0xffffffffu, g, off);
        }
        if (l == 0) {
            shf[w] = f;
            shb[w] = g;
        }
        __syncthreads();
        if (tid == 0) {
            float tf = 0.f, tb = 0.f;
#pragma unroll
            for (int ww = 0; ww < 8; ww++) {
                tf += shf[ww];
                tb += shb[ww];
            }
            g_mfg[b * Dm + e] = tf;
            g_mbg[b * Dm + e] = tb;
        }
        return;
    }
    // dot phase
    __shared__ float qs[32 * 257];
    __shared__ float vbuf[8][264];
    __shared__ float warpP[8][33];
    int db = blk - 1024;
    int task = db >> 2, sg = db & 3;
    int b = task >> 1;
    const float* projb = g_proj + (size_t)b * HW * 256;

    for (int q = 0; q < 4; q++) {
        int a = w * 4 + q;
        const float* src = projb + (size_t)g_aidx[task * 32 + a] * 256;
        float v[8], ss = 0.f;
#pragma unroll
        for (int cc = 0; cc < 8; cc++) {
            v[cc] = src[l + 32 * cc];
            ss = fmaf(v[cc], v[cc], ss);
        }
#pragma unroll
        for (int off = 16; off; off >>= 1) ss += __shfl_xor_sync(0xffffffffu, ss, off);
        float sc = 1.f / fmaxf(sqrtf(ss), 1e-12f);
#pragma unroll
        for (int cc = 0; cc < 8; cc++) qs[a * 257 + l + 32 * cc] = v[cc] * sc;
    }
    __syncthreads();

    float accv = 0.f;
    for (int q = 0; q < 4; q++) {
        int s = sg * 32 + w + q * 8;
        bool isP = s < 64;
        int si = isP ? s : s - 64;
        float fl = isP ? g_pflag[task * 64 + si] : g_nflag[task * 64 + si];
        if (fl != 0.f) {
            int idx = isP ? g_pidx[task * 64 + si] : g_nidx[task * 64 + si];
            const float* src = projb + (size_t)idx * 256;
            float v[8], ss = 0.f;
#pragma unroll
            for (int cc = 0; cc < 8; cc++) {
                v[cc] = src[l + 32 * cc];
                ss = fmaf(v[cc], v[cc], ss);
            }
#pragma unroll
            for (int off = 16; off; off >>= 1) ss += __shfl_xor_sync(0xffffffffu, ss, off);
            float sc = 1.f / fmaxf(sqrtf(ss), 1e-12f);
#pragma unroll
            for (int cc = 0; cc < 8; cc++) vbuf[w][l + 32 * cc] = v[cc] * sc;
            __syncwarp();
            float dot = 0.f;
            const float* qrow = &qs[l * 257];
#pragma unroll 8
            for (int d = 0; d < 256; d++) dot = fmaf(qrow[d], vbuf[w][d], dot);
            accv += expf(dot * 10.f);
            __syncwarp();
        }
    }
    warpP[w][l] = accv;
    __syncthreads();
    if (w == 0) {
        float p = 0.f;
#pragma unroll
        for (int ww = 0; ww < 8; ww++) p += warpP[ww][l];
        g_dacc[(task * 4 + sg) * 32 + l] = p;
    }
}

// ---------------- final: pair finalize + local + global loss -----------------
__global__ __launch_bounds__(256) void k_final(float* __restrict__ out, int out_size) {
    __shared__ float scratch[34];
    __shared__ float qf[4][257], qb[4][257];
    __shared__ float cf[4], cb[4];
    __shared__ float pfv[4], pbv[4], nfv[4], nbv[4];
    __shared__ float sbl[8];
    __shared__ int sinc[8];
    int tid = threadIdx.x;

    {
        int task = tid >> 5, l = tid & 31;
        float p = g_dacc[(task * 4 + 0) * 32 + l] + g_dacc[(task * 4 + 1) * 32 + l];
        float n = g_dacc[(task * 4 + 2) * 32 + l] + g_dacc[(task * 4 + 3) * 32 + l];
        bool inc = (g_cA[task] >= 1) && (g_cB[task] >= 1);
        if (!inc) p += 1.f;
        float per = -logf(p / (p + n + 1e-8f));
        float af = g_aflag[task * 32 + l];
        float ws = per * af, as = af;
#pragma unroll
        for (int off = 16; off; off >>= 1) {
            ws += __shfl_down_sync(0xffffffffu, ws, off);
            as += __shfl_down_sync(0xffffffffu, as, off);
        }
        if (l == 0) {
            sbl[task] = inc ? (ws / fmaxf(as, 1.f)) : 0.f;
            sinc[task] = inc ? 1 : 0;
        }
    }
    __syncthreads();

    for (int b = 0; b < 4; b++) {
        float c1 = 0.f, c0 = 0.f;
        for (int i = tid; i < HW; i += 256) {
            c1 += (float)g_m1[b * HW + i];
            c0 += (float)g_m0[b * HW + i];
        }
        float s1 = blk_sum(scratch, c1, tid);
        float s0 = blk_sum(scratch, c0, tid);
        if (tid == 0) { cf[b] = s1; cb[b] = s0; }
    }
    __syncthreads();

    for (int b = 0; b < 4; b++) {
        float mf = g_mfg[b * Dm + tid] / fmaxf(cf[b], 1.f);
        float mb_ = g_mbg[b * Dm + tid] / fmaxf(cb[b], 1.f);
        float ssf = blk_sum(scratch, mf * mf, tid);
        qf[b][tid] = mf / fmaxf(sqrtf(ssf), 1e-12f);
        float ssb = blk_sum(scratch, mb_ * mb_, tid);
        qb[b][tid] = mb_ / fmaxf(sqrtf(ssb), 1e-12f);
    }
    __syncthreads();

    for (int b = 0; b < 4; b++) {
        float d1 = blk_sum(scratch, qf[b][tid] * qf[b][tid], tid);
        float d2 = blk_sum(scratch, qb[b][tid] * qb[b][tid], tid);
        if (tid == 0) {
            pfv[b] = expf(d1 * 10.f);
            pbv[b] = expf(d2 * 10.f);
            nfv[b] = 0.f;
            nbv[b] = 0.f;
        }
        __syncthreads();
    }
    for (int b = 0; b < 4; b++) {
        for (int j = 0; j <= b; j++) {
            float dqbqf = blk_sum(scratch, qb[j][tid] * qf[b][tid], tid);
            float dqfqb = blk_sum(scratch, qf[j][tid] * qb[b][tid], tid);
            if (tid == 0) {
                bool vgj = (cf[j] >= 1.f) && (cb[j] >= 1.f);
                if (vgj) {
                    nfv[b] += expf(dqbqf * 10.f);
                    nbv[b] += expf(dqfqb * 10.f);
                }
            }
            __syncthreads();
        }
    }

    if (tid == 0) {
        float lsum = 0.f;
        int icnt = 0;
        for (int t = 0; t < 8; t++) {
            lsum += sbl[t];
            icnt += sinc[t];
        }
        float l_local = lsum / (float)max(icnt, 1);
        float gs = 0.f;
        int vcnt = 0;
        for (int b = 0; b < 4; b++) {
            bool vg = (cf[b] >= 1.f) && (cb[b] >= 1.f);
            if (vg) {
                float lg = -logf(pfv[b] / (pfv[b] + nfv[b] + 1e-8f)) -
                           logf(pbv[b] / (pbv[b] + nbv[b] + 1e-8f));
                gs += lg;
                vcnt++;
            }
        }
        float l_global = gs / (float)max(vcnt, 1);
        if (out_size > 0) out[0] = l_local + 0.5f * l_global;
        if (out_size > 1) out[1] = l_local;
        if (out_size > 2) out[2] = l_global;
    }
}

// ---------------- launch ------------------------------------------------------
extern "C" void kernel_launch(void* const* d_in, const int* in_sizes, int n_in, void* d_out,
                              int out_size) {
    const float* feat = (const float*)d_in[0];
    const int* labels = (const int*)d_in[1];
    const float* prob_ori = (const float*)d_in[2];
    const float* prob_aug = (const float*)d_in[3];
    const float* unc = (const float*)d_in[4];
    const float* r_anc = (const float*)d_in[5];
    const float* r_pos = (const float*)d_in[6];
    const float* r_neg = (const float*)d_in[7];
    const float* w1 = (const float*)d_in[8];
    const float* b1 = (const float*)d_in[9];
    const float* gamma = (const float*)d_in[10];
    const float* beta = (const float*)d_in[11];
    const float* w2 = (const float*)d_in[12];
    const float* b2 = (const float*)d_in[13];

    cudaFuncSetAttribute(k_gemm_mma<false>, cudaFuncAttributeMaxDynamicSharedMemorySize,
                         GEMM_SMEM);
    cudaFuncSetAttribute(k_gemm_mma<true>, cudaFuncAttributeMaxDynamicSharedMemorySize,
                         GEMM_SMEM);

    k_pre<<<384 + 4096, 256>>>(prob_ori, prob_aug, unc, labels, w1, w2, feat);
    k_gemm_mma<false><<<8 + NBLK * 2 * Bm, 256, GEMM_SMEM>>>(b1, unc, r_anc, r_pos, r_neg);
    k_finstats<<<Dm, 128>>>(gamma, beta);
    k_bnsplit<<<Bm * HW / 16, 256>>>();
    k_gemm_mma<true><<<NBLK * 2 * Bm, 256, GEMM_SMEM>>>(b2, nullptr, nullptr, nullptr, nullptr);
    k_tail<<<1024 + 32, 256>>>();
    k_final<<<1, 256>>>((float*)d_out, out_size);
}